// round 17
// baseline (speedup 1.0000x reference)
#include <cuda_runtime.h>
#include <cuda_bf16.h>
#include <cstdint>

// FlowNet correlation — R16 (= R15 design, infra retry): tf32 banded
// parity-space Gram, 2 CTAs/SM, B-fragment PAIR-PACKING (5 ldsV2 ->
// 2 ldsV4 + 1 ldsV2 per warp/ks) and next-chunk prefetch issued BEFORE the
// per-dy epilogue STG burst.
// out[b, dyi*21+dxi, h, w] = (1/256) * sum_c in1[b,c,h,w] * in2[b,c,h+dy,w+dx]
// CTA = (b, h, parity): 128 threads, 4 rb-warps.

#define CB   8
#define CC_  256
#define HH   96
#define WW   128
#define GG   21
#define DD   441
#define NTASK (HH * CB * 2)   // 1536 (b,h,par)
#define NCTA  296

#define QBLOB  131072L     // per (b,h): [par][kc][rb][ks] x 512B A-fragments
#define KCHUNK 49152L      // per (r,kc): [par][pair q0..5][ks] x 512B records
#define KPART  24576       // per-parity half of a K chunk (6 pairs x 8 ks x 512)
#define KBLOB  (4 * KCHUNK) // per (b,r)

#define QOFF   0
#define KOFF   65536       // per-parity Q = 64KB
#define SMEM_REQ 114816    // 65536 + 2*24576 + 128 align slack

__device__ __align__(128) char g1[(long)CB * HH * QBLOB];
__device__ __align__(128) char g2[(long)CB * HH * KBLOB];

// ---------------- helpers ----------------
__device__ __forceinline__ uint32_t smem_u32(const void* p) {
    uint32_t a;
    asm("{ .reg .u64 t; cvta.to.shared.u64 t, %1; cvt.u32.u64 %0, t; }"
        : "=r"(a) : "l"(p));
    return a;
}
__device__ __forceinline__ void cp16(uint32_t dst, const void* src) {
    asm volatile("cp.async.cg.shared.global [%0], [%1], 16;"
                 :: "r"(dst), "l"(src));
}
__device__ __forceinline__ void cp_commit() {
    asm volatile("cp.async.commit_group;" ::: "memory");
}
__device__ __forceinline__ void cp_wait1() {
    asm volatile("cp.async.wait_group 1;" ::: "memory");
}
__device__ __forceinline__ void cp_wait0() {
    asm volatile("cp.async.wait_group 0;" ::: "memory");
}
__device__ __forceinline__ void ldsV4(uint32_t r[4], uint32_t addr) {
    asm volatile("ld.shared.v4.u32 {%0,%1,%2,%3}, [%4];"
        : "=r"(r[0]), "=r"(r[1]), "=r"(r[2]), "=r"(r[3]) : "r"(addr));
}
__device__ __forceinline__ void ldsV2(uint32_t r[2], uint32_t addr) {
    asm volatile("ld.shared.v2.u32 {%0,%1}, [%2];"
        : "=r"(r[0]), "=r"(r[1]) : "r"(addr));
}
__device__ __forceinline__ void mma_tf32(float c[4], const uint32_t a[4],
                                         const uint32_t b0, const uint32_t b1) {
    asm volatile("mma.sync.aligned.m16n8k8.row.col.f32.tf32.tf32.f32 "
        "{%0,%1,%2,%3}, {%4,%5,%6,%7}, {%8,%9}, {%0,%1,%2,%3};"
        : "+f"(c[0]), "+f"(c[1]), "+f"(c[2]), "+f"(c[3])
        : "r"(a[0]), "r"(a[1]), "r"(a[2]), "r"(a[3]), "r"(b0), "r"(b1));
}
__device__ __forceinline__ uint32_t f2tf32(float v) {
    uint32_t r;
    asm("cvt.rna.tf32.f32 %0, %1;" : "=r"(r) : "f"(v));
    return r;
}

// ---------------- prepass: fp32 -> fragment-packed tf32 ----------------
__global__ __launch_bounds__(256)
void prep_kernel(const float* __restrict__ in1,
                 const float* __restrict__ in2)
{
    __shared__ float st[64][133];
    const int kc = blockIdx.x, hh = blockIdx.y;
    const int b = blockIdx.z >> 1, inp = blockIdx.z & 1;
    const float* src = inp ? in2 : in1;

    for (int i = threadIdx.x; i < 64 * 32; i += 256) {
        const int c = i >> 5, q = i & 31;
        const float4 v = *reinterpret_cast<const float4*>(
            src + (((long)(b * CC_ + kc * 64 + c)) * HH + hh) * WW + 4 * q);
        st[c][4*q+0] = v.x; st[c][4*q+1] = v.y;
        st[c][4*q+2] = v.z; st[c][4*q+3] = v.w;
    }
    __syncthreads();

    if (!inp) {
        // A fragments: m16k8, per-lane 16B
        char* base = g1 + (long)(b * HH + hh) * QBLOB;
        for (int e = threadIdx.x; e < 2048; e += 256) {
            const int lane = e & 31;
            const int ks = (e >> 5) & 7;
            const int rb = (e >> 8) & 3;
            const int par = e >> 10;
            const int row = 16 * rb + (lane >> 2);
            const int cl = 8 * ks + (lane & 3);
            const int w0 = 2 * row + par;
            const int w1 = 2 * (row + 8) + par;
            uint4 v;
            v.x = f2tf32(st[cl][w0]);
            v.y = f2tf32(st[cl][w1]);
            v.z = f2tf32(st[cl + 4][w0]);
            v.w = f2tf32(st[cl + 4][w1]);
            *reinterpret_cast<uint4*>(
                base + (long)((((par*4 + kc)*4 + rb)*8 + ks) * 512 + lane * 16)) = v;
        }
    } else {
        // B fragments PAIR-PACKED: record = [tile u=2q 8B][tile u=2q+1 8B]
        // per lane; q = 0..5 (u=11 half is zero).
        char* base = g2 + (long)(b * HH + hh) * KBLOB + (long)kc * KCHUNK;
        for (int e = threadIdx.x; e < 3072; e += 256) {
            const int lane = e & 31;
            const int ks = (e >> 5) & 7;
            const int q = (e >> 8) % 6;
            const int par = e / 1536;
            const int n = lane >> 2;
            const int cl = 8 * ks + (lane & 3);
            uint4 v = make_uint4(0u, 0u, 0u, 0u);
            const int j0 = 8 * (2 * q) - 10 + n;        // tile u=2q
            if ((unsigned)j0 < 64u) {
                const int w = 2 * j0 + par;
                v.x = f2tf32(st[cl][w]);
                v.y = f2tf32(st[cl + 4][w]);
            }
            const int u1 = 2 * q + 1;
            if (u1 < 11) {
                const int j1 = 8 * u1 - 10 + n;         // tile u=2q+1
                if ((unsigned)j1 < 64u) {
                    const int w = 2 * j1 + par;
                    v.z = f2tf32(st[cl][w]);
                    v.w = f2tf32(st[cl + 4][w]);
                }
            }
            *reinterpret_cast<uint4*>(
                base + (long)(((par*6 + q)*8 + ks) * 512 + lane * 16)) = v;
        }
    }
}

// ---------------- main kernel (persistent, 128 threads, 2 CTAs/SM) --------
__global__ __launch_bounds__(128, 2)
void corr_mma_kernel(float* __restrict__ out)
{
    extern __shared__ char smraw[];
    const uint32_t rawS = smem_u32(smraw);
    const uint32_t smb = (rawS + 127) & ~127u;

    const int tid = threadIdx.x, lane = tid & 31, rb = tid >> 5;
    const int i0 = rb * 16;

    const float scale = 1.0f / 256.0f;
    const int r0l = lane >> 2, n0l = (lane & 3) * 2;

    const uint32_t aLane = (uint32_t)lane * 16;
    const uint32_t bLane = (uint32_t)lane * 16;

    float C[5][4];
#pragma unroll
    for (int t = 0; t < 5; ++t)
#pragma unroll
        for (int g = 0; g < 4; ++g) C[t][g] = 0.0f;

    for (int g = blockIdx.x; g < NTASK; g += NCTA) {
        const int p = g & 1;
        const int b = (g >> 1) & 7;
        const int h = g >> 4;

        const int dyimin = (h >= 20) ? 0 : ((21 - h) >> 1);
        const int dyimax = min(20, (115 - h) >> 1);
        const int nv = dyimax - dyimin + 1;
        const int NC = 4 * nv;

        const long obase_bh = (long)b * DD * HH * WW + (long)h * WW;

        // zero this parity's elements of invalid-dy planes
        for (int dyi = 0; dyi < GG; ++dyi) {
            if (dyi >= dyimin && dyi <= dyimax) continue;
            const long pb = obase_bh + (long)(dyi * GG) * (HH * WW);
            for (int e = tid; e < GG * 64; e += 128) {
                out[pb + (long)(e >> 6) * (HH * WW) + 2 * (e & 63) + p] = 0.0f;
            }
        }

        auto issueK = [&](int c, int stage) {
            const int vidx = c >> 2, kc = c & 3;
            const int r = h + 2 * (dyimin + vidx) - 20;
            const char* src = g2 + (long)(b * HH + r) * KBLOB
                            + (long)kc * KCHUNK + (long)p * KPART;
            const uint32_t dst = smb + KOFF + (uint32_t)stage * KPART;
#pragma unroll
            for (int o = 0; o < 12; ++o) {
                const int t = tid + 128 * o;
                cp16(dst + (uint32_t)t * 16, src + (long)t * 16);
            }
            cp_commit();
        };

        // prologue: Q (+K0) as group 0, K1 as group 1
        {
            const char* qsrc = g1 + (long)(b * HH + h) * QBLOB + (long)p * 65536;
#pragma unroll
            for (int o = 0; o < 32; ++o) {
                const int t = tid + 128 * o;
                cp16(smb + QOFF + (uint32_t)t * 16, qsrc + (long)t * 16);
            }
            const int r0v = h + 2 * dyimin - 20;
            const char* ks = g2 + (long)(b * HH + r0v) * KBLOB + (long)p * KPART;
            const uint32_t dst = smb + KOFF;
#pragma unroll
            for (int o = 0; o < 12; ++o) {
                const int t = tid + 128 * o;
                cp16(dst + (uint32_t)t * 16, ks + (long)t * 16);
            }
            cp_commit();
            issueK(1, 1);
        }

        for (int c = 0; c < NC; ++c) {
            if (c + 1 < NC) cp_wait1(); else cp_wait0();
            __syncthreads();                   // stage (c&1) visible CTA-wide

            // ---- compute chunk c: 8 ksteps x 5 tiles of m16n8k8 tf32 ----
            // warp rb: pairs q=rb (tiles 2rb,2rb+1), q=rb+1 (2rb+2,2rb+3),
            //          q=rb+2 first half (tile 2rb+4)
            {
                const int kc = c & 3;
                const uint32_t aBase = smb + QOFF
                    + (uint32_t)((kc*4 + rb)*8) * 512 + aLane;
                const uint32_t bBase = smb + KOFF + (uint32_t)(c & 1) * KPART
                    + bLane;
#pragma unroll
                for (int ks = 0; ks < 8; ++ks) {
                    uint32_t af[4], b01[4], b23[4], b4[2];
                    ldsV4(af,  aBase + (uint32_t)ks * 512);
                    ldsV4(b01, bBase + (uint32_t)((rb    )*8 + ks) * 512);
                    ldsV4(b23, bBase + (uint32_t)((rb + 1)*8 + ks) * 512);
                    ldsV2(b4,  bBase + (uint32_t)((rb + 2)*8 + ks) * 512);
                    mma_tf32(C[0], af, b01[0], b01[1]);
                    mma_tf32(C[1], af, b01[2], b01[3]);
                    mma_tf32(C[2], af, b23[0], b23[1]);
                    mma_tf32(C[3], af, b23[2], b23[3]);
                    mma_tf32(C[4], af, b4[0],  b4[1]);
                }
            }

            __syncthreads();                   // stage (c&1) drained
            if (c + 2 < NC) issueK(c + 2, c & 1);   // prefetch BEFORE epilogue

            // ---- epilogue after last kc of a dy: direct predicated STG ----
            if ((c & 3) == 3) {
                const int dyi = dyimin + (c >> 2);
                const long pb = obase_bh + (long)(dyi * GG) * (HH * WW);
#pragma unroll
                for (int t = 0; t < 5; ++t)
#pragma unroll
                    for (int g4 = 0; g4 < 4; ++g4) {
                        const int row = r0l + ((g4 & 2) ? 8 : 0);
                        const int col = n0l + (g4 & 1);
                        const int dxi = 8 * t + col - row;
                        if (dxi >= 0 && dxi < GG)
                            out[pb + (long)dxi * (HH * WW) + 2 * (i0 + row) + p]
                                = C[t][g4] * scale;
                        C[t][g4] = 0.0f;
                    }
            }
        }
    }
}

extern "C" void kernel_launch(void* const* d_in, const int* in_sizes, int n_in,
                              void* d_out, int out_size)
{
    const float* in1 = (const float*)d_in[0];
    const float* in2 = (const float*)d_in[1];
    float* out = (float*)d_out;
    (void)in_sizes; (void)n_in; (void)out_size;

    cudaFuncSetAttribute(corr_mma_kernel,
                         cudaFuncAttributeMaxDynamicSharedMemorySize, SMEM_REQ);

    dim3 pgrid(4, HH, CB * 2);
    prep_kernel<<<pgrid, 256>>>(in1, in2);

    corr_mma_kernel<<<NCTA, 128, SMEM_REQ>>>(out);
}